// round 15
// baseline (speedup 1.0000x reference)
#include <cuda_runtime.h>
#include <cuda_fp16.h>
#include <cstdint>

#define D     128
#define NMAX  800000
#define GMAX  4096
#define MT    64          // rows per tile (per warp-group)
#define WROW  68          // weight row stride (words; 64 data + 4 pad, 16B-aligned rows)
#define XROW  68          // X/H row stride (words)
#define NBLK  152
#define NTHR  512

// ------------------------------- scratch -----------------------------------
__device__ float  g_w[NMAX];
__device__ __half g_pf[(size_t)NMAX * D];
__device__ int    g_start[GMAX + 1];

// ---------------------------- smem word offsets -----------------------------
#define W_ARR   (128 * WROW)             // 8704 words
#define OFF_W1  0
#define OFF_WW  (1 * W_ARR)
#define OFF_W2  (2 * W_ARR)
#define OFF_XG  (3 * W_ARR)              // + gid*8704 : X(4352) then H(4352)
#define OFF_PG  (5 * W_ARR)              // + gid*4352 : pf staging (64 x 68)
#define SMEM_WORDS (5 * W_ARR + 2 * 64 * XROW)   // 52224 words = 208896 B

#define GBAR(id) asm volatile("bar.sync %0, 256;" :: "r"(id) : "memory")

// ------------------------------ helpers -------------------------------------
__device__ __forceinline__ uint32_t hpack(float a, float b) {
    __half2 h = __floats2half2_rn(a, b);
    return *reinterpret_cast<uint32_t*>(&h);
}
// packed silu: r = vh*tanh(vh) + vh with vh = 0.5v  (= 0.5v(1+tanh(0.5v)))
__device__ __forceinline__ uint32_t silu2_bits(float a, float b) {
    __half2 v  = __floats2half2_rn(a, b);
    __half2 vh = __hmul2(v, __float2half2_rn(0.5f));
    uint32_t t;
    asm("tanh.approx.f16x2 %0, %1;" : "=r"(t) : "r"(*reinterpret_cast<uint32_t*>(&vh)));
    __half2 th = *reinterpret_cast<__half2*>(&t);
    __half2 r  = __hfma2(vh, th, vh);
    return *reinterpret_cast<uint32_t*>(&r);
}
__device__ __forceinline__ float2 silu2_f(float a, float b) {
    uint32_t u = silu2_bits(a, b);
    return __half22float2(*reinterpret_cast<__half2*>(&u));
}

// D[16x8] += A[16x16] * B[16x8]; fp16 in, fp32 accum
__device__ __forceinline__ void mma_f16(float c[4],
    uint32_t a0, uint32_t a1, uint32_t a2, uint32_t a3, uint32_t b0, uint32_t b1)
{
    asm volatile(
        "mma.sync.aligned.m16n8k16.row.col.f32.f16.f16.f32 "
        "{%0,%1,%2,%3}, {%4,%5,%6,%7}, {%8,%9}, {%0,%1,%2,%3};\n"
        : "+f"(c[0]), "+f"(c[1]), "+f"(c[2]), "+f"(c[3])
        : "r"(a0), "r"(a1), "r"(a2), "r"(a3), "r"(b0), "r"(b1));
}

__device__ __forceinline__ void ldsm4(uint32_t* r, uint32_t addr) {
    asm volatile("ldmatrix.sync.aligned.m8n8.x4.shared.b16 {%0,%1,%2,%3}, [%4];"
        : "=r"(r[0]), "=r"(r[1]), "=r"(r[2]), "=r"(r[3]) : "r"(addr));
}

// fused dual sweep: cw += A@Ww1^T, cf += A@Wf1^T (A shared), warp tile 32x32
__device__ __forceinline__ void sweep12(uint32_t abase, uint32_t bWW, uint32_t bW1,
                                        float cw[2][4][4], float cf[2][4][4])
{
#pragma unroll
    for (int ks = 0; ks < 8; ks++) {
        uint32_t ah[8];
        ldsm4(ah,     abase + ks * 32);
        ldsm4(ah + 4, abase + 16 * XROW * 4 + ks * 32);
#pragma unroll
        for (int p = 0; p < 2; p++) {
            uint32_t bw[4], bf[4];
            ldsm4(bw, bWW + p * (16 * WROW * 4) + ks * 32);
            mma_f16(cw[0][2 * p],     ah[0], ah[1], ah[2], ah[3], bw[0], bw[1]);
            mma_f16(cw[0][2 * p + 1], ah[0], ah[1], ah[2], ah[3], bw[2], bw[3]);
            mma_f16(cw[1][2 * p],     ah[4], ah[5], ah[6], ah[7], bw[0], bw[1]);
            mma_f16(cw[1][2 * p + 1], ah[4], ah[5], ah[6], ah[7], bw[2], bw[3]);
            ldsm4(bf, bW1 + p * (16 * WROW * 4) + ks * 32);
            mma_f16(cf[0][2 * p],     ah[0], ah[1], ah[2], ah[3], bf[0], bf[1]);
            mma_f16(cf[0][2 * p + 1], ah[0], ah[1], ah[2], ah[3], bf[2], bf[3]);
            mma_f16(cf[1][2 * p],     ah[4], ah[5], ah[6], ah[7], bf[0], bf[1]);
            mma_f16(cf[1][2 * p + 1], ah[4], ah[5], ah[6], ah[7], bf[2], bf[3]);
        }
    }
}

// single sweep: c += A@B^T
__device__ __forceinline__ void sweep1(uint32_t abase, uint32_t bbase, float c[2][4][4])
{
#pragma unroll
    for (int ks = 0; ks < 8; ks++) {
        uint32_t ah[8];
        ldsm4(ah,     abase + ks * 32);
        ldsm4(ah + 4, abase + 16 * XROW * 4 + ks * 32);
#pragma unroll
        for (int p = 0; p < 2; p++) {
            uint32_t b[4];
            ldsm4(b, bbase + p * (16 * WROW * 4) + ks * 32);
            mma_f16(c[0][2 * p],     ah[0], ah[1], ah[2], ah[3], b[0], b[1]);
            mma_f16(c[0][2 * p + 1], ah[0], ah[1], ah[2], ah[3], b[2], b[3]);
            mma_f16(c[1][2 * p],     ah[4], ah[5], ah[6], ah[7], b[0], b[1]);
            mma_f16(c[1][2 * p + 1], ah[4], ah[5], ah[6], ah[7], b[2], b[3]);
        }
    }
}

// --------------------------- segment bounds ---------------------------------
__global__ void k_bounds(const int* __restrict__ idx, int n, int G) {
    int i = blockIdx.x * blockDim.x + threadIdx.x;
    if (i >= n) return;
    int b = idx[i];
    int bp = (i == 0) ? -1 : idx[i - 1];
    for (int g = bp + 1; g <= b; g++) g_start[g] = i;
    if (i == n - 1) for (int g = b + 1; g <= G; g++) g_start[g] = n;
}

// --------------------------- fused MLP kernel --------------------------------
// 512 threads = 2 independent groups of 8 warps; each group streams its own
// 64-row tiles with group-scoped barriers (phase-skew fills pipe bubbles).
__global__ __launch_bounds__(NTHR, 1) void k_fused(
    const float* __restrict__ X,
    const float* __restrict__ Wf1, const float* __restrict__ bf1,
    const float* __restrict__ Wf2, const float* __restrict__ bf2,
    const float* __restrict__ Ww1, const float* __restrict__ bw1,
    const float* __restrict__ Ww2, const float* __restrict__ bw2,
    int n, int ntiles)
{
    extern __shared__ uint32_t sw[];
    __shared__ float sbf1[D], sbw1[D], sbf2[D], sWw2[D];
    __shared__ float wred[2][MT][4];
    __shared__ float sbw2v;

    const int tid  = threadIdx.x;
    const int gid  = tid >> 8;       // group 0/1
    const int gtid = tid & 255;
    const int lane = tid & 31;
    const int gwid = (tid >> 5) & 7;
    const int g    = lane >> 2;      // 0..7
    const int t_   = lane & 3;       // 0..3
    const int m0   = (gwid & 1) * 32;
    const int nq   = gwid >> 1;      // 0..3
    const int n0   = nq * 32;
    const int bar  = gid + 1;

    const int OFF_X = OFF_XG + gid * 8704;
    const int OFF_H = OFF_X + MT * XROW;     // 4352
    const int OFF_P = OFF_PG + gid * 4352;

    const uint32_t sb = (uint32_t)__cvta_generic_to_shared(sw);
    const uint32_t arel = (uint32_t)(((m0 + (lane & 15)) * XROW + ((lane >> 4) * 4)) * 4);
    const uint32_t abase = sb + OFF_X * 4 + arel;
    const uint32_t hbase = sb + OFF_H * 4 + arel;
    const uint32_t brel = (uint32_t)(((n0 + ((lane >> 4) * 8) + (lane & 7)) * WROW
                                      + ((lane >> 3) & 1) * 4) * 4);
    const uint32_t bWW = sb + OFF_WW * 4 + brel;
    const uint32_t bW1 = sb + OFF_W1 * 4 + brel;
    const uint32_t bW2 = sb + OFF_W2 * 4 + brel;

    // ---- convert weights to transposed fp16 in smem (whole block) ----
    {
        const float* srcs[3] = {Ww1, Wf1, Wf2};
        const int offs[3] = {OFF_WW, OFF_W1, OFF_W2};
#pragma unroll
        for (int s = 0; s < 3; s++) {
            const float* Wsrc = srcs[s];
            for (int i = tid; i < 128 * 64; i += NTHR) {
                int k2 = i >> 7, nn = i & 127;
                float v0 = Wsrc[(2 * k2) * D + nn];
                float v1 = Wsrc[(2 * k2 + 1) * D + nn];
                sw[offs[s] + nn * WROW + k2] = hpack(v0, v1);
            }
        }
    }
    if (tid < D) { sbf1[tid] = bf1[tid]; sbw1[tid] = bw1[tid]; sbf2[tid] = bf2[tid]; sWw2[tid] = Ww2[tid]; }
    if (tid == 0) sbw2v = bw2[0];
    __syncthreads();   // last block-wide sync; groups diverge below

    const long long nworkers = (long long)gridDim.x * 2;
    const long long worker   = (long long)blockIdx.x * 2 + gid;

    // X gmem mapping: 8 float4 per thread, converted to fp16 pairs at load
    const int xr = gtid >> 5, xq0 = (gtid & 31);   // i = gtid + kq*256 -> r = i>>5 = xr + kq*8
    uint32_t xh[16];

    auto prefetchX = [&](long long tt) {
#pragma unroll
        for (int kq = 0; kq < 8; kq++) {
            int r = xr + kq * 8, q = xq0;
            long long node = tt * MT + r;
            bool v = (tt < (long long)ntiles) && (node < n);
            float4 x = v ? __ldg((const float4*)(X + node * D) + q)
                         : make_float4(0.f, 0.f, 0.f, 0.f);
            xh[2 * kq]     = hpack(x.x, x.y);
            xh[2 * kq + 1] = hpack(x.z, x.w);
        }
    };
    auto storeX = [&]() {
#pragma unroll
        for (int kq = 0; kq < 8; kq++) {
            int r = xr + kq * 8, q = xq0;
            *(uint2*)&sw[OFF_X + r * XROW + 2 * q] = make_uint2(xh[2 * kq], xh[2 * kq + 1]);
        }
    };

    // prologue: fill first X tile
    prefetchX(worker);
    storeX();
    prefetchX(worker + nworkers);
    GBAR(bar);

    for (long long t = worker; t < ntiles; t += nworkers) {
        const long long tb = t * MT;

        // ---- fused sweeps 1+2: Hw = X@Ww1^T, Hf = X@Wf1^T ----
        float cw[2][4][4], cf[2][4][4];
#pragma unroll
        for (int s = 0; s < 2; s++)
#pragma unroll
            for (int nt = 0; nt < 4; nt++)
#pragma unroll
                for (int j = 0; j < 4; j++) { cw[s][nt][j] = 0.f; cf[s][nt][j] = 0.f; }
        sweep12(abase, bWW, bW1, cw, cf);

        // ---- w epilogue: packed silu + dot(Ww2), fp32 accumulation ----
        {
            float pw[2][2];
            pw[0][0] = pw[0][1] = pw[1][0] = pw[1][1] = 0.f;
#pragma unroll
            for (int s = 0; s < 2; s++)
#pragma unroll
                for (int nt = 0; nt < 4; nt++) {
                    int c0 = n0 + nt * 8 + 2 * t_;
                    float2 h0 = silu2_f(cw[s][nt][0] + sbw1[c0], cw[s][nt][1] + sbw1[c0 + 1]);
                    float2 h1 = silu2_f(cw[s][nt][2] + sbw1[c0], cw[s][nt][3] + sbw1[c0 + 1]);
                    pw[s][0] = fmaf(h0.x, sWw2[c0],     pw[s][0]);
                    pw[s][0] = fmaf(h0.y, sWw2[c0 + 1], pw[s][0]);
                    pw[s][1] = fmaf(h1.x, sWw2[c0],     pw[s][1]);
                    pw[s][1] = fmaf(h1.y, sWw2[c0 + 1], pw[s][1]);
                }
#pragma unroll
            for (int s = 0; s < 2; s++)
#pragma unroll
                for (int h = 0; h < 2; h++) {
                    pw[s][h] += __shfl_xor_sync(0xffffffffu, pw[s][h], 1);
                    pw[s][h] += __shfl_xor_sync(0xffffffffu, pw[s][h], 2);
                }
            if (t_ == 0) {
                wred[gid][m0 + g][nq]          = pw[0][0];
                wred[gid][m0 + g + 8][nq]      = pw[0][1];
                wred[gid][m0 + 16 + g][nq]     = pw[1][0];
                wred[gid][m0 + 16 + g + 8][nq] = pw[1][1];
            }
        }

        // ---- H = silu(Hf + bf1) packed -> fp16 into HBUF ----
#pragma unroll
        for (int s = 0; s < 2; s++)
#pragma unroll
            for (int nt = 0; nt < 4; nt++) {
                int c0 = n0 + nt * 8 + 2 * t_;
                int widx = (n0 >> 1) + nt * 4 + t_;
                int r0 = m0 + s * 16 + g, r1 = r0 + 8;
                sw[OFF_H + r0 * XROW + widx] =
                    silu2_bits(cf[s][nt][0] + sbf1[c0], cf[s][nt][1] + sbf1[c0 + 1]);
                sw[OFF_H + r1 * XROW + widx] =
                    silu2_bits(cf[s][nt][2] + sbf1[c0], cf[s][nt][3] + sbf1[c0 + 1]);
            }
        GBAR(bar);   // (1) sweep12 done by all (X free), H + wred visible

        // ---- store next tile's X (overlaps sweep3 phase) ----
        storeX();

        if (gtid < MT) {
            long long node = tb + gtid;
            if (node < n)
                g_w[node] = sbw2v + wred[gid][gtid][0] + wred[gid][gtid][1]
                                  + wred[gid][gtid][2] + wred[gid][gtid][3];
        }

        // ---- sweep 3: pf = H @ Wf2^T ----
        float cp[2][4][4];
#pragma unroll
        for (int s = 0; s < 2; s++)
#pragma unroll
            for (int nt = 0; nt < 4; nt++)
#pragma unroll
                for (int j = 0; j < 4; j++) cp[s][nt][j] = 0.f;
        sweep1(hbase, bW2, cp);

        // ---- prefetch X for tile t+2*nworkers ----
        prefetchX(t + 2 * nworkers);
        GBAR(bar);   // (2) next X visible, sweep3 done (H free)

        // ---- pf epilogue: stage into warp-private PBUF, then coalesced STG ----
#pragma unroll
        for (int s = 0; s < 2; s++) {
#pragma unroll
            for (int nt = 0; nt < 4; nt++) {
                int c0 = n0 + nt * 8 + 2 * t_;
                int word = (n0 >> 1) + nt * 4 + t_;
                int r0 = m0 + s * 16 + g, r1 = r0 + 8;
                sw[OFF_P + r0 * XROW + word] =
                    hpack(cp[s][nt][0] + sbf2[c0], cp[s][nt][1] + sbf2[c0 + 1]);
                sw[OFF_P + r1 * XROW + word] =
                    hpack(cp[s][nt][2] + sbf2[c0], cp[s][nt][3] + sbf2[c0 + 1]);
            }
        }
        __syncwarp();
        // warp reads only its own rows m0..m0+31, cols n0..n0+31 (16 words/row)
#pragma unroll
        for (int it = 0; it < 4; it++) {
            int c  = lane + it * 32;          // 0..127
            int rl = m0 + (c >> 2);           // 32 rows
            int off = c & 3;                  // 4 x 16B per row
            uint4 v = *(const uint4*)&sw[OFF_P + rl * XROW + (n0 >> 1) + off * 4];
            long long row = tb + rl;
            if (row < n)
                *(uint4*)(g_pf + row * D + n0 + off * 8) = v;
        }
    }
}

// --------------------------- per-graph softmax + pool ------------------------
// one warp per graph: shfl-only reductions, no block barriers
__global__ __launch_bounds__(256) void k_pool(float* __restrict__ out, int n, int G)
{
    const int gidx = blockIdx.x * 8 + (threadIdx.x >> 5);
    if (gidx >= G) return;
    const int lane = threadIdx.x & 31;
    const int s = g_start[gidx], e = g_start[gidx + 1];

    float m = -3.4e38f;
    for (int i = s + lane; i < e; i += 32) m = fmaxf(m, g_w[i]);
#pragma unroll
    for (int o = 16; o; o >>= 1) m = fmaxf(m, __shfl_xor_sync(0xffffffffu, m, o));

    float sum = 0.f;
    for (int i = s + lane; i < e; i += 32) sum += __expf(g_w[i] - m);
#pragma unroll
    for (int o = 16; o; o >>= 1) sum += __shfl_xor_sync(0xffffffffu, sum, o);
    const float inv = 1.0f / (sum + 1e-16f);

    // weighted pool: lane covers cols {2lane, 2lane+1, 64+2lane, 65+2lane}
    float4 acc = make_float4(0.f, 0.f, 0.f, 0.f);
    const __half2* base = (const __half2*)g_pf;
    int j = s;
    for (; j + 2 <= e; j += 2) {
        float c0 = __expf(g_w[j]     - m) * inv;
        float c1 = __expf(g_w[j + 1] - m) * inv;
        float2 v00 = __half22float2(base[(size_t)j * 64 + lane]);
        float2 v01 = __half22float2(base[(size_t)j * 64 + 32 + lane]);
        float2 v10 = __half22float2(base[(size_t)(j + 1) * 64 + lane]);
        float2 v11 = __half22float2(base[(size_t)(j + 1) * 64 + 32 + lane]);
        acc.x = fmaf(v00.x, c0, acc.x);  acc.y = fmaf(v00.y, c0, acc.y);
        acc.z = fmaf(v01.x, c0, acc.z);  acc.w = fmaf(v01.y, c0, acc.w);
        acc.x = fmaf(v10.x, c1, acc.x);  acc.y = fmaf(v10.y, c1, acc.y);
        acc.z = fmaf(v11.x, c1, acc.z);  acc.w = fmaf(v11.y, c1, acc.w);
    }
    if (j < e) {
        float c0 = __expf(g_w[j] - m) * inv;
        float2 v00 = __half22float2(base[(size_t)j * 64 + lane]);
        float2 v01 = __half22float2(base[(size_t)j * 64 + 32 + lane]);
        acc.x = fmaf(v00.x, c0, acc.x);  acc.y = fmaf(v00.y, c0, acc.y);
        acc.z = fmaf(v01.x, c0, acc.z);  acc.w = fmaf(v01.y, c0, acc.w);
    }
    float* orow = out + (size_t)gidx * D;
    *(float2*)(orow + 2 * lane)      = make_float2(acc.x, acc.y);
    *(float2*)(orow + 64 + 2 * lane) = make_float2(acc.z, acc.w);
}

// ----------------------------------------------------------------------------
extern "C" void kernel_launch(void* const* d_in, const int* in_sizes, int n_in,
                              void* d_out, int out_size)
{
    const float* X   = (const float*)d_in[0];
    const int*   idx = (const int*)  d_in[1];
    const float* Wf1 = (const float*)d_in[2];
    const float* bf1 = (const float*)d_in[3];
    const float* Wf2 = (const float*)d_in[4];
    const float* bf2 = (const float*)d_in[5];
    const float* Ww1 = (const float*)d_in[6];
    const float* bw1 = (const float*)d_in[7];
    const float* Ww2 = (const float*)d_in[8];
    const float* bw2 = (const float*)d_in[9];
    float* out = (float*)d_out;

    int n = in_sizes[1];
    int G = out_size / D;
    int ntiles = (n + MT - 1) / MT;

    size_t smb = (size_t)SMEM_WORDS * sizeof(uint32_t);   // 208896 B
    cudaFuncSetAttribute(k_fused, cudaFuncAttributeMaxDynamicSharedMemorySize, (int)smb);

    // k_fused first (doesn't use g_start) — also keeps ncu's capture slot on it
    k_fused<<<NBLK, NTHR, smb>>>(X, Wf1, bf1, Wf2, bf2, Ww1, bw1, Ww2, bw2, n, ntiles);
    k_bounds<<<(n + 255) / 256, 256>>>(idx, n, G);
    k_pool<<<(G + 7) / 8, 256>>>(out, n, G);
}

// round 16
// speedup vs baseline: 1.1311x; 1.1311x over previous
#include <cuda_runtime.h>
#include <cuda_fp16.h>
#include <cstdint>

#define D     128
#define NMAX  800000
#define GMAX  4096
#define MT    32          // rows per tile (per warp-group)
#define WROW  68          // weight row stride (words; 64 data + 4 pad, 16B-aligned rows)
#define XROW  68          // X/H row stride (words)
#define NBLK  152
#define NTHR  512

// ------------------------------- scratch -----------------------------------
__device__ float  g_w[NMAX];
__device__ __half g_pf[(size_t)NMAX * D];
__device__ int    g_start[GMAX + 1];

// ---------------------------- smem word offsets -----------------------------
#define W_ARR   (128 * WROW)             // 8704 words
#define OFF_W1  0
#define OFF_WW  (1 * W_ARR)
#define OFF_W2  (2 * W_ARR)
#define OFF_XG  (3 * W_ARR)              // + gid*4352 : X(2176) then H(2176)
#define SMEM_WORDS (3 * W_ARR + 4 * 4352)   // 43520 words = 174080 B

#define GBAR(id) asm volatile("bar.sync %0, 128;" :: "r"(id) : "memory")

// ------------------------------ helpers -------------------------------------
__device__ __forceinline__ uint32_t hpack(float a, float b) {
    __half2 h = __floats2half2_rn(a, b);
    return *reinterpret_cast<uint32_t*>(&h);
}
// packed silu: r = vh*tanh(vh) + vh with vh = 0.5v  (= 0.5v(1+tanh(0.5v)))
__device__ __forceinline__ uint32_t silu2_bits(float a, float b) {
    __half2 v  = __floats2half2_rn(a, b);
    __half2 vh = __hmul2(v, __float2half2_rn(0.5f));
    uint32_t t;
    asm("tanh.approx.f16x2 %0, %1;" : "=r"(t) : "r"(*reinterpret_cast<uint32_t*>(&vh)));
    __half2 th = *reinterpret_cast<__half2*>(&t);
    __half2 r  = __hfma2(vh, th, vh);
    return *reinterpret_cast<uint32_t*>(&r);
}
__device__ __forceinline__ float2 silu2_f(float a, float b) {
    uint32_t u = silu2_bits(a, b);
    return __half22float2(*reinterpret_cast<__half2*>(&u));
}

// D[16x8] += A[16x16] * B[16x8]; fp16 in, fp32 accum
__device__ __forceinline__ void mma_f16(float c[4],
    uint32_t a0, uint32_t a1, uint32_t a2, uint32_t a3, uint32_t b0, uint32_t b1)
{
    asm volatile(
        "mma.sync.aligned.m16n8k16.row.col.f32.f16.f16.f32 "
        "{%0,%1,%2,%3}, {%4,%5,%6,%7}, {%8,%9}, {%0,%1,%2,%3};\n"
        : "+f"(c[0]), "+f"(c[1]), "+f"(c[2]), "+f"(c[3])
        : "r"(a0), "r"(a1), "r"(a2), "r"(a3), "r"(b0), "r"(b1));
}

__device__ __forceinline__ void ldsm4(uint32_t* r, uint32_t addr) {
    asm volatile("ldmatrix.sync.aligned.m8n8.x4.shared.b16 {%0,%1,%2,%3}, [%4];"
        : "=r"(r[0]), "=r"(r[1]), "=r"(r[2]), "=r"(r[3]) : "r"(addr));
}

// fused dual sweep: cw += A@Ww1^T, cf += A@Wf1^T (A shared), warp tile 32x32
__device__ __forceinline__ void sweep12(uint32_t abase, uint32_t bWW, uint32_t bW1,
                                        float cw[2][4][4], float cf[2][4][4])
{
#pragma unroll
    for (int ks = 0; ks < 8; ks++) {
        uint32_t ah[8];
        ldsm4(ah,     abase + ks * 32);
        ldsm4(ah + 4, abase + 16 * XROW * 4 + ks * 32);
#pragma unroll
        for (int p = 0; p < 2; p++) {
            uint32_t bw[4], bf[4];
            ldsm4(bw, bWW + p * (16 * WROW * 4) + ks * 32);
            mma_f16(cw[0][2 * p],     ah[0], ah[1], ah[2], ah[3], bw[0], bw[1]);
            mma_f16(cw[0][2 * p + 1], ah[0], ah[1], ah[2], ah[3], bw[2], bw[3]);
            mma_f16(cw[1][2 * p],     ah[4], ah[5], ah[6], ah[7], bw[0], bw[1]);
            mma_f16(cw[1][2 * p + 1], ah[4], ah[5], ah[6], ah[7], bw[2], bw[3]);
            ldsm4(bf, bW1 + p * (16 * WROW * 4) + ks * 32);
            mma_f16(cf[0][2 * p],     ah[0], ah[1], ah[2], ah[3], bf[0], bf[1]);
            mma_f16(cf[0][2 * p + 1], ah[0], ah[1], ah[2], ah[3], bf[2], bf[3]);
            mma_f16(cf[1][2 * p],     ah[4], ah[5], ah[6], ah[7], bf[0], bf[1]);
            mma_f16(cf[1][2 * p + 1], ah[4], ah[5], ah[6], ah[7], bf[2], bf[3]);
        }
    }
}

// single sweep: c += A@B^T
__device__ __forceinline__ void sweep1(uint32_t abase, uint32_t bbase, float c[2][4][4])
{
#pragma unroll
    for (int ks = 0; ks < 8; ks++) {
        uint32_t ah[8];
        ldsm4(ah,     abase + ks * 32);
        ldsm4(ah + 4, abase + 16 * XROW * 4 + ks * 32);
#pragma unroll
        for (int p = 0; p < 2; p++) {
            uint32_t b[4];
            ldsm4(b, bbase + p * (16 * WROW * 4) + ks * 32);
            mma_f16(c[0][2 * p],     ah[0], ah[1], ah[2], ah[3], b[0], b[1]);
            mma_f16(c[0][2 * p + 1], ah[0], ah[1], ah[2], ah[3], b[2], b[3]);
            mma_f16(c[1][2 * p],     ah[4], ah[5], ah[6], ah[7], b[0], b[1]);
            mma_f16(c[1][2 * p + 1], ah[4], ah[5], ah[6], ah[7], b[2], b[3]);
        }
    }
}

// --------------------------- segment bounds ---------------------------------
__global__ void k_bounds(const int* __restrict__ idx, int n, int G) {
    int i = blockIdx.x * blockDim.x + threadIdx.x;
    if (i >= n) return;
    int b = idx[i];
    int bp = (i == 0) ? -1 : idx[i - 1];
    for (int g = bp + 1; g <= b; g++) g_start[g] = i;
    if (i == n - 1) for (int g = b + 1; g <= G; g++) g_start[g] = n;
}

// --------------------------- fused MLP kernel --------------------------------
// 512 threads = 4 independent groups of 4 warps (1 warp/SMSP/group); each group
// streams its own 32-row tiles with group-scoped barriers. Max phase diversity:
// 4 independent MMA/epilogue streams per SMSP.
__global__ __launch_bounds__(NTHR, 1) void k_fused(
    const float* __restrict__ X,
    const float* __restrict__ Wf1, const float* __restrict__ bf1,
    const float* __restrict__ Wf2, const float* __restrict__ bf2,
    const float* __restrict__ Ww1, const float* __restrict__ bw1,
    const float* __restrict__ Ww2, const float* __restrict__ bw2,
    int n, int ntiles)
{
    extern __shared__ uint32_t sw[];
    __shared__ float sbf1[D], sbw1[D], sbf2[D], sWw2[D];
    __shared__ float wred[4][MT][4];
    __shared__ float sbw2v;

    const int tid  = threadIdx.x;
    const int gid  = tid >> 7;       // group 0..3
    const int gtid = tid & 127;
    const int lane = tid & 31;
    const int g    = lane >> 2;      // 0..7
    const int t_   = lane & 3;       // 0..3
    const int nq   = (tid >> 5) & 3; // warp-in-group = n-quarter
    const int n0   = nq * 32;
    const int bar  = gid + 1;

    const int OFF_X = OFF_XG + gid * 4352;
    const int OFF_H = OFF_X + MT * XROW;     // 2176

    const uint32_t sb = (uint32_t)__cvta_generic_to_shared(sw);
    const uint32_t arel = (uint32_t)((((lane & 15)) * XROW + ((lane >> 4) * 4)) * 4);
    const uint32_t abase = sb + OFF_X * 4 + arel;
    const uint32_t hbase = sb + OFF_H * 4 + arel;
    const uint32_t brel = (uint32_t)(((n0 + ((lane >> 4) * 8) + (lane & 7)) * WROW
                                      + ((lane >> 3) & 1) * 4) * 4);
    const uint32_t bWW = sb + OFF_WW * 4 + brel;
    const uint32_t bW1 = sb + OFF_W1 * 4 + brel;
    const uint32_t bW2 = sb + OFF_W2 * 4 + brel;

    // ---- convert weights to transposed fp16 in smem (whole block) ----
    {
        const float* srcs[3] = {Ww1, Wf1, Wf2};
        const int offs[3] = {OFF_WW, OFF_W1, OFF_W2};
#pragma unroll
        for (int s = 0; s < 3; s++) {
            const float* Wsrc = srcs[s];
            for (int i = tid; i < 128 * 64; i += NTHR) {
                int k2 = i >> 7, nn = i & 127;
                float v0 = Wsrc[(2 * k2) * D + nn];
                float v1 = Wsrc[(2 * k2 + 1) * D + nn];
                sw[offs[s] + nn * WROW + k2] = hpack(v0, v1);
            }
        }
    }
    if (tid < D) { sbf1[tid] = bf1[tid]; sbw1[tid] = bw1[tid]; sbf2[tid] = bf2[tid]; sWw2[tid] = Ww2[tid]; }
    if (tid == 0) sbw2v = bw2[0];
    __syncthreads();   // last block-wide sync; groups diverge below

    const long long nworkers = (long long)gridDim.x * 4;
    const long long worker   = (long long)blockIdx.x * 4 + gid;

    // X gmem mapping: 8 float4 per thread; i = gtid + kq*128 -> r = (gtid>>5)+kq*4
    const int xr = gtid >> 5, xq0 = gtid & 31;
    uint32_t xh[16];

    auto prefetchX = [&](long long tt) {
#pragma unroll
        for (int kq = 0; kq < 8; kq++) {
            int r = xr + kq * 4, q = xq0;
            long long node = tt * MT + r;
            bool v = (tt < (long long)ntiles) && (node < n);
            float4 x = v ? __ldg((const float4*)(X + node * D) + q)
                         : make_float4(0.f, 0.f, 0.f, 0.f);
            xh[2 * kq]     = hpack(x.x, x.y);
            xh[2 * kq + 1] = hpack(x.z, x.w);
        }
    };
    auto storeX = [&]() {
#pragma unroll
        for (int kq = 0; kq < 8; kq++) {
            int r = xr + kq * 4, q = xq0;
            *(uint2*)&sw[OFF_X + r * XROW + 2 * q] = make_uint2(xh[2 * kq], xh[2 * kq + 1]);
        }
    };

    // prologue: fill first X tile
    prefetchX(worker);
    storeX();
    prefetchX(worker + nworkers);
    GBAR(bar);

    for (long long t = worker; t < ntiles; t += nworkers) {
        const long long tb = t * MT;

        // ---- fused sweeps 1+2: Hw = X@Ww1^T, Hf = X@Wf1^T ----
        float cw[2][4][4], cf[2][4][4];
#pragma unroll
        for (int s = 0; s < 2; s++)
#pragma unroll
            for (int nt = 0; nt < 4; nt++)
#pragma unroll
                for (int j = 0; j < 4; j++) { cw[s][nt][j] = 0.f; cf[s][nt][j] = 0.f; }
        sweep12(abase, bWW, bW1, cw, cf);

        // ---- w epilogue: packed silu + dot(Ww2), fp32 accumulation ----
        {
            float pw[2][2];
            pw[0][0] = pw[0][1] = pw[1][0] = pw[1][1] = 0.f;
#pragma unroll
            for (int s = 0; s < 2; s++)
#pragma unroll
                for (int nt = 0; nt < 4; nt++) {
                    int c0 = n0 + nt * 8 + 2 * t_;
                    float2 h0 = silu2_f(cw[s][nt][0] + sbw1[c0], cw[s][nt][1] + sbw1[c0 + 1]);
                    float2 h1 = silu2_f(cw[s][nt][2] + sbw1[c0], cw[s][nt][3] + sbw1[c0 + 1]);
                    pw[s][0] = fmaf(h0.x, sWw2[c0],     pw[s][0]);
                    pw[s][0] = fmaf(h0.y, sWw2[c0 + 1], pw[s][0]);
                    pw[s][1] = fmaf(h1.x, sWw2[c0],     pw[s][1]);
                    pw[s][1] = fmaf(h1.y, sWw2[c0 + 1], pw[s][1]);
                }
#pragma unroll
            for (int s = 0; s < 2; s++)
#pragma unroll
                for (int h = 0; h < 2; h++) {
                    pw[s][h] += __shfl_xor_sync(0xffffffffu, pw[s][h], 1);
                    pw[s][h] += __shfl_xor_sync(0xffffffffu, pw[s][h], 2);
                }
            if (t_ == 0) {
                wred[gid][g][nq]          = pw[0][0];
                wred[gid][g + 8][nq]      = pw[0][1];
                wred[gid][16 + g][nq]     = pw[1][0];
                wred[gid][16 + g + 8][nq] = pw[1][1];
            }
        }

        // ---- H = silu(Hf + bf1) packed -> fp16 into HBUF ----
#pragma unroll
        for (int s = 0; s < 2; s++)
#pragma unroll
            for (int nt = 0; nt < 4; nt++) {
                int c0 = n0 + nt * 8 + 2 * t_;
                int widx = (n0 >> 1) + nt * 4 + t_;
                int r0 = s * 16 + g, r1 = r0 + 8;
                sw[OFF_H + r0 * XROW + widx] =
                    silu2_bits(cf[s][nt][0] + sbf1[c0], cf[s][nt][1] + sbf1[c0 + 1]);
                sw[OFF_H + r1 * XROW + widx] =
                    silu2_bits(cf[s][nt][2] + sbf1[c0], cf[s][nt][3] + sbf1[c0 + 1]);
            }
        GBAR(bar);   // (1) sweep12 done by group (X free), H + wred visible

        // ---- store next tile's X (overlaps sweep3 phase) ----
        storeX();

        if (gtid < MT) {
            long long node = tb + gtid;
            if (node < n)
                g_w[node] = sbw2v + wred[gid][gtid][0] + wred[gid][gtid][1]
                                  + wred[gid][gtid][2] + wred[gid][gtid][3];
        }

        // ---- sweep 3: pf = H @ Wf2^T ----
        float cp[2][4][4];
#pragma unroll
        for (int s = 0; s < 2; s++)
#pragma unroll
            for (int nt = 0; nt < 4; nt++)
#pragma unroll
                for (int j = 0; j < 4; j++) cp[s][nt][j] = 0.f;
        sweep1(hbase, bW2, cp);

        // ---- prefetch X for tile t+2*nworkers ----
        prefetchX(t + 2 * nworkers);
        GBAR(bar);   // (2) next X visible, sweep3 done (H free)

        // ---- pf epilogue -> g_pf (fp16), registers only ----
#pragma unroll
        for (int s = 0; s < 2; s++) {
            long long r0 = tb + s * 16 + g;
            long long r1 = r0 + 8;
#pragma unroll
            for (int nt = 0; nt < 4; nt++) {
                int c0 = n0 + nt * 8 + 2 * t_;
                if (r0 < n)
                    *(uint32_t*)(g_pf + r0 * D + c0) =
                        hpack(cp[s][nt][0] + sbf2[c0], cp[s][nt][1] + sbf2[c0 + 1]);
                if (r1 < n)
                    *(uint32_t*)(g_pf + r1 * D + c0) =
                        hpack(cp[s][nt][2] + sbf2[c0], cp[s][nt][3] + sbf2[c0 + 1]);
            }
        }
    }
}

// --------------------------- per-graph softmax + pool ------------------------
// 256 threads: col-pair = tid&63 (half2), row-group = tid>>6 (stride 4 rows)
__global__ __launch_bounds__(256) void k_pool(float* __restrict__ out, int n)
{
    const int g = blockIdx.x, tid = threadIdx.x, lane = tid & 31, wid = tid >> 5;
    const int c2 = tid & 63, rg = tid >> 6;   // rg 0..3
    const int s = g_start[g], e = g_start[g + 1];
    __shared__ float  redm[8], reds[8], scoef[128];
    __shared__ float2 sacc[4][64];

    float m = -3.4e38f;
    for (int i = s + tid; i < e; i += 256) m = fmaxf(m, g_w[i]);
#pragma unroll
    for (int o = 16; o; o >>= 1) m = fmaxf(m, __shfl_xor_sync(0xffffffffu, m, o));
    if (lane == 0) redm[wid] = m;
    __syncthreads();
    m = fmaxf(fmaxf(fmaxf(redm[0], redm[1]), fmaxf(redm[2], redm[3])),
              fmaxf(fmaxf(redm[4], redm[5]), fmaxf(redm[6], redm[7])));

    float sum = 0.f;
    for (int i = s + tid; i < e; i += 256) sum += __expf(g_w[i] - m);
#pragma unroll
    for (int o = 16; o; o >>= 1) sum += __shfl_xor_sync(0xffffffffu, sum, o);
    if (lane == 0) reds[wid] = sum;
    __syncthreads();
    sum = reds[0] + reds[1] + reds[2] + reds[3] + reds[4] + reds[5] + reds[6] + reds[7];
    const float inv = 1.0f / (sum + 1e-16f);

    float2 acc0 = make_float2(0.f, 0.f), acc1 = make_float2(0.f, 0.f);
    for (int i0 = s; i0 < e; i0 += 128) {
        int cnt = min(128, e - i0);
        __syncthreads();
        if (tid < 128) scoef[tid] = (tid < cnt) ? __expf(g_w[i0 + tid] - m) * inv : 0.f;
        __syncthreads();
        const __half2* p = (const __half2*)(g_pf + (size_t)i0 * D) + c2;
        int j = rg;
        for (; j + 4 < cnt; j += 8) {
            float2 v0 = __half22float2(p[(size_t)j * 64]);
            float2 v1 = __half22float2(p[(size_t)(j + 4) * 64]);
            float cc0 = scoef[j], cc1 = scoef[j + 4];
            acc0.x = fmaf(v0.x, cc0, acc0.x);
            acc0.y = fmaf(v0.y, cc0, acc0.y);
            acc1.x = fmaf(v1.x, cc1, acc1.x);
            acc1.y = fmaf(v1.y, cc1, acc1.y);
        }
        for (; j < cnt; j += 4) {
            float2 v = __half22float2(p[(size_t)j * 64]);
            float c = scoef[j];
            acc0.x = fmaf(v.x, c, acc0.x);
            acc0.y = fmaf(v.y, c, acc0.y);
        }
    }
    __syncthreads();
    sacc[rg][c2] = make_float2(acc0.x + acc1.x, acc0.y + acc1.y);
    __syncthreads();
    if (rg == 0) {
        float2 a0 = sacc[0][c2], a1 = sacc[1][c2], a2 = sacc[2][c2], a3 = sacc[3][c2];
        float2 o;
        o.x = (a0.x + a1.x) + (a2.x + a3.x);
        o.y = (a0.y + a1.y) + (a2.y + a3.y);
        *(float2*)(out + (size_t)g * D + 2 * c2) = o;
    }
}

// ----------------------------------------------------------------------------
extern "C" void kernel_launch(void* const* d_in, const int* in_sizes, int n_in,
                              void* d_out, int out_size)
{
    const float* X   = (const float*)d_in[0];
    const int*   idx = (const int*)  d_in[1];
    const float* Wf1 = (const float*)d_in[2];
    const float* bf1 = (const float*)d_in[3];
    const float* Wf2 = (const float*)d_in[4];
    const float* bf2 = (const float*)d_in[5];
    const float* Ww1 = (const float*)d_in[6];
    const float* bw1 = (const float*)d_in[7];
    const float* Ww2 = (const float*)d_in[8];
    const float* bw2 = (const float*)d_in[9];
    float* out = (float*)d_out;

    int n = in_sizes[1];
    int G = out_size / D;
    int ntiles = (n + MT - 1) / MT;

    size_t smb = (size_t)SMEM_WORDS * sizeof(uint32_t);   // 174080 B
    cudaFuncSetAttribute(k_fused, cudaFuncAttributeMaxDynamicSharedMemorySize, (int)smb);

    // k_fused first (doesn't use g_start) — keeps ncu's capture slot on it
    k_fused<<<NBLK, NTHR, smb>>>(X, Wf1, bf1, Wf2, bf2, Ww1, bw1, Ww2, bw2, n, ntiles);
    k_bounds<<<(n + 255) / 256, 256>>>(idx, n, G);
    k_pool<<<G, 256>>>(out, n);
}